// round 5
// baseline (speedup 1.0000x reference)
#include <cuda_runtime.h>
#include <cuda_bf16.h>
#include <cstdint>
#include <math.h>

#define Bb 2
#define Ss 2048
#define Hh 1024
#define NHh 16
#define Dd 64
#define MROWS (Bb * Ss)   // 4096

// Scratch (no cudaMalloc allowed): Q, K, V, ctx each [4096, 1024] fp32 = 16 MiB
__device__ float g_q[MROWS * Hh];
__device__ float g_k[MROWS * Hh];
__device__ float g_v[MROWS * Hh];
__device__ float g_ctx[MROWS * Hh];

// ===========================================================================
// Helpers: ldmatrix + mma.sync (compute_103-safe PTX, runs on HMMA pipe)
// ===========================================================================
__device__ __forceinline__ uint32_t smem_u32(const void* p) {
    uint32_t a;
    asm("{ .reg .u64 t; cvta.to.shared.u64 t, %1; cvt.u32.u64 %0, t; }"
        : "=r"(a) : "l"(p));
    return a;
}

__device__ __forceinline__ void ldm4(uint32_t* r, uint32_t addr) {
    asm volatile("ldmatrix.sync.aligned.m8n8.x4.shared.b16 {%0,%1,%2,%3}, [%4];"
                 : "=r"(r[0]), "=r"(r[1]), "=r"(r[2]), "=r"(r[3])
                 : "r"(addr));
}

__device__ __forceinline__ void mma_bf16(float* d, const uint32_t* a,
                                         uint32_t b0, uint32_t b1) {
    asm volatile(
        "mma.sync.aligned.m16n8k16.row.col.f32.bf16.bf16.f32 "
        "{%0,%1,%2,%3}, {%4,%5,%6,%7}, {%8,%9}, {%0,%1,%2,%3};"
        : "+f"(d[0]), "+f"(d[1]), "+f"(d[2]), "+f"(d[3])
        : "r"(a[0]), "r"(a[1]), "r"(a[2]), "r"(a[3]), "r"(b0), "r"(b1));
}

// fp32 -> (hi bf16x2, lo bf16x2) hi/lo split of a float4
__device__ __forceinline__ void split4(float4 v, uint2& hi, uint2& lo) {
    __nv_bfloat162 h01 = __float22bfloat162_rn(make_float2(v.x, v.y));
    __nv_bfloat162 h23 = __float22bfloat162_rn(make_float2(v.z, v.w));
    uint32_t u01 = *reinterpret_cast<uint32_t*>(&h01);
    uint32_t u23 = *reinterpret_cast<uint32_t*>(&h23);
    float rx = v.x - __uint_as_float(u01 << 16);
    float ry = v.y - __uint_as_float(u01 & 0xFFFF0000u);
    float rz = v.z - __uint_as_float(u23 << 16);
    float rw = v.w - __uint_as_float(u23 & 0xFFFF0000u);
    __nv_bfloat162 l01 = __float22bfloat162_rn(make_float2(rx, ry));
    __nv_bfloat162 l23 = __float22bfloat162_rn(make_float2(rz, rw));
    hi = make_uint2(u01, u23);
    lo = make_uint2(*reinterpret_cast<uint32_t*>(&l01),
                    *reinterpret_cast<uint32_t*>(&l23));
}

// ===========================================================================
// Tensor-core GEMM (NT): C[m][n] = sum_k A[m][k]*W[n][k] + bias[n]
// M=4096, N=1024, K=1024. CTA 128x128, 8 warps (2Mx4N), warp 64x32, Kc=32.
// fp32 accuracy via bf16 hi/lo split: C += Ahi*Bhi + Ahi*Blo + Alo*Bhi.
// ===========================================================================
__global__ void __launch_bounds__(256) gemm_tc(
    const float* __restrict__ A, const float* __restrict__ W,
    const float* __restrict__ bias, float* __restrict__ C)
{
    // rows padded to 40 bf16 (80 B): ldmatrix bank pattern (r*20)%32 is
    // conflict-free across the 8 row-addresses.
    __shared__ uint32_t sAhi[128][20], sAlo[128][20];
    __shared__ uint32_t sBhi[128][20], sBlo[128][20];

    const int tid  = threadIdx.x;
    const int wid  = tid >> 5;
    const int lane = tid & 31;
    const int m0 = blockIdx.y * 128;
    const int n0 = blockIdx.x * 128;
    const int wm = (wid & 1) * 64;     // warp M offset
    const int wn = (wid >> 1) * 32;    // warp N offset

    float acc[4][4][4];
#pragma unroll
    for (int i = 0; i < 4; i++)
#pragma unroll
        for (int j = 0; j < 4; j++)
#pragma unroll
            for (int c = 0; c < 4; c++) acc[i][j][c] = 0.f;

    // ldmatrix lane->address decomposition
    const int a_row = lane & 15;
    const int a_col = (lane >> 4) << 3;
    const int b_row = (lane & 7) + ((lane >> 4) & 1) * 8;
    const int b_col = ((lane >> 3) & 1) << 3;

    const uint32_t pAhi = smem_u32(sAhi), pAlo = smem_u32(sAlo);
    const uint32_t pBhi = smem_u32(sBhi), pBlo = smem_u32(sBlo);

    for (int k0 = 0; k0 < 1024; k0 += 32) {
        // Load + split + store: A and B each 128 rows x 32 cols fp32
#pragma unroll
        for (int t = 0; t < 4; t++) {
            int i  = tid + t * 256;
            int r  = i >> 3;
            int c4 = (i & 7) << 2;     // 0..28
            int ci = c4 >> 1;          // uint32 index

            float4 va = *(const float4*)&A[(size_t)(m0 + r) * 1024 + k0 + c4];
            uint2 h, l;
            split4(va, h, l);
            *(uint2*)&sAhi[r][ci] = h;
            *(uint2*)&sAlo[r][ci] = l;

            float4 vb = *(const float4*)&W[(size_t)(n0 + r) * 1024 + k0 + c4];
            split4(vb, h, l);
            *(uint2*)&sBhi[r][ci] = h;
            *(uint2*)&sBlo[r][ci] = l;
        }
        __syncthreads();

#pragma unroll
        for (int kk = 0; kk < 32; kk += 16) {
            uint32_t ahi[4][4], alo[4][4], bhi[8], blo[8];
#pragma unroll
            for (int mt = 0; mt < 4; mt++) {
                uint32_t off = (uint32_t)((wm + mt * 16 + a_row) * 80 +
                                          (kk + a_col) * 2);
                ldm4(ahi[mt], pAhi + off);
                ldm4(alo[mt], pAlo + off);
            }
#pragma unroll
            for (int np = 0; np < 2; np++) {
                uint32_t off = (uint32_t)((wn + np * 16 + b_row) * 80 +
                                          (kk + b_col) * 2);
                ldm4(&bhi[np * 4], pBhi + off);
                ldm4(&blo[np * 4], pBlo + off);
            }
#pragma unroll
            for (int mt = 0; mt < 4; mt++)
#pragma unroll
                for (int ng = 0; ng < 4; ng++) {
                    mma_bf16(acc[mt][ng], ahi[mt], bhi[ng * 2], bhi[ng * 2 + 1]);
                    mma_bf16(acc[mt][ng], ahi[mt], blo[ng * 2], blo[ng * 2 + 1]);
                    mma_bf16(acc[mt][ng], alo[mt], bhi[ng * 2], bhi[ng * 2 + 1]);
                }
        }
        __syncthreads();
    }

    // Epilogue: C[m16n8] frag: lane g=l/4,t=l%4 -> c0,c1 @ (g, 2t), c2,c3 @ (g+8, 2t)
    const int g = lane >> 2;
    const int t = lane & 3;
#pragma unroll
    for (int mt = 0; mt < 4; mt++) {
#pragma unroll
        for (int ng = 0; ng < 4; ng++) {
            int row = m0 + wm + mt * 16 + g;
            int col = n0 + wn + ng * 8 + t * 2;
            float2 bv = *(const float2*)&bias[col];
            float2 o0, o1;
            o0.x = acc[mt][ng][0] + bv.x;
            o0.y = acc[mt][ng][1] + bv.y;
            o1.x = acc[mt][ng][2] + bv.x;
            o1.y = acc[mt][ng][3] + bv.y;
            *(float2*)&C[(size_t)row * 1024 + col]       = o0;
            *(float2*)&C[(size_t)(row + 8) * 1024 + col] = o1;
        }
    }
}

// ---------------------------------------------------------------------------
// Flash attention (unchanged, known correct): Br=64, Bc=32, online softmax.
// ---------------------------------------------------------------------------
__global__ void __launch_bounds__(256) attn_kernel()
{
    const int bh = blockIdx.y;           // 0..31
    const int b  = bh / NHh;
    const int h  = bh % NHh;
    const int q0 = blockIdx.x * 64;

    __shared__ float sQ[64][68];
    __shared__ float sK[32][68];
    __shared__ float sV[32][68];
    __shared__ float sP[64][36];

    const int tid = threadIdx.x;
    const float* Qb = g_q + (size_t)(b * Ss) * Hh + h * Dd;
    const float* Kb = g_k + (size_t)(b * Ss) * Hh + h * Dd;
    const float* Vb = g_v + (size_t)(b * Ss) * Hh + h * Dd;

    for (int i = tid; i < 64 * 16; i += 256) {
        int r = i / 16, c4 = (i % 16) * 4;
        *(float4*)&sQ[r][c4] = *(const float4*)&Qb[(size_t)(q0 + r) * Hh + c4];
    }

    const int r  = tid / 4;
    const int cg = tid % 4;

    float m = -1e30f, l = 0.f;
    float o[16];
#pragma unroll
    for (int j = 0; j < 16; j++) o[j] = 0.f;

    for (int kt = 0; kt < Ss; kt += 32) {
        __syncthreads();
        for (int i = tid; i < 32 * 16; i += 256) {
            int rr = i / 16, c4 = (i % 16) * 4;
            *(float4*)&sK[rr][c4] = *(const float4*)&Kb[(size_t)(kt + rr) * Hh + c4];
            *(float4*)&sV[rr][c4] = *(const float4*)&Vb[(size_t)(kt + rr) * Hh + c4];
        }
        __syncthreads();

        float s[8];
#pragma unroll
        for (int c = 0; c < 8; c++) s[c] = 0.f;
#pragma unroll
        for (int d4 = 0; d4 < 64; d4 += 4) {
            float4 qv = *(const float4*)&sQ[r][d4];
#pragma unroll
            for (int c = 0; c < 8; c++) {
                float4 kv = *(const float4*)&sK[cg * 8 + c][d4];
                s[c] = fmaf(qv.x, kv.x, s[c]);
                s[c] = fmaf(qv.y, kv.y, s[c]);
                s[c] = fmaf(qv.z, kv.z, s[c]);
                s[c] = fmaf(qv.w, kv.w, s[c]);
            }
        }

        float mt = -1e30f;
#pragma unroll
        for (int c = 0; c < 8; c++) {
            s[c] *= 0.125f;
            mt = fmaxf(mt, s[c]);
        }
        mt = fmaxf(mt, __shfl_xor_sync(0xffffffffu, mt, 1));
        mt = fmaxf(mt, __shfl_xor_sync(0xffffffffu, mt, 2));

        float mnew  = fmaxf(m, mt);
        float alpha = __expf(m - mnew);
        float ls = 0.f;
#pragma unroll
        for (int c = 0; c < 8; c++) {
            float p = __expf(s[c] - mnew);
            ls += p;
            sP[r][cg * 8 + c] = p;
        }
        ls += __shfl_xor_sync(0xffffffffu, ls, 1);
        ls += __shfl_xor_sync(0xffffffffu, ls, 2);
        l = l * alpha + ls;
        m = mnew;
#pragma unroll
        for (int j = 0; j < 16; j++) o[j] *= alpha;

        __syncthreads();

#pragma unroll
        for (int k = 0; k < 32; k++) {
            float p = sP[r][k];
            float4 v0 = *(const float4*)&sV[k][cg * 16 + 0];
            float4 v1 = *(const float4*)&sV[k][cg * 16 + 4];
            float4 v2 = *(const float4*)&sV[k][cg * 16 + 8];
            float4 v3 = *(const float4*)&sV[k][cg * 16 + 12];
            o[0]  = fmaf(p, v0.x, o[0]);  o[1]  = fmaf(p, v0.y, o[1]);
            o[2]  = fmaf(p, v0.z, o[2]);  o[3]  = fmaf(p, v0.w, o[3]);
            o[4]  = fmaf(p, v1.x, o[4]);  o[5]  = fmaf(p, v1.y, o[5]);
            o[6]  = fmaf(p, v1.z, o[6]);  o[7]  = fmaf(p, v1.w, o[7]);
            o[8]  = fmaf(p, v2.x, o[8]);  o[9]  = fmaf(p, v2.y, o[9]);
            o[10] = fmaf(p, v2.z, o[10]); o[11] = fmaf(p, v2.w, o[11]);
            o[12] = fmaf(p, v3.x, o[12]); o[13] = fmaf(p, v3.y, o[13]);
            o[14] = fmaf(p, v3.z, o[14]); o[15] = fmaf(p, v3.w, o[15]);
        }
    }

    const float inv = 1.f / l;
    float* outp = g_ctx + (size_t)(b * Ss + q0 + r) * Hh + h * Dd + cg * 16;
#pragma unroll
    for (int j = 0; j < 16; j += 4) {
        float4 c;
        c.x = o[j + 0] * inv; c.y = o[j + 1] * inv;
        c.z = o[j + 2] * inv; c.w = o[j + 3] * inv;
        *(float4*)&outp[j] = c;
    }
}

// ---------------------------------------------------------------------------
extern "C" void kernel_launch(void* const* d_in, const int* in_sizes, int n_in,
                              void* d_out, int out_size)
{
    const float* x  = (const float*)d_in[0];
    const float* wq = (const float*)d_in[1];
    const float* bq = (const float*)d_in[2];
    const float* wk = (const float*)d_in[3];
    const float* bk = (const float*)d_in[4];
    const float* wv = (const float*)d_in[5];
    const float* bv = (const float*)d_in[6];
    const float* wo = (const float*)d_in[7];
    const float* bo = (const float*)d_in[8];
    float* out = (float*)d_out;

    float *q, *k, *v, *ctx;
    cudaGetSymbolAddress((void**)&q,   g_q);
    cudaGetSymbolAddress((void**)&k,   g_k);
    cudaGetSymbolAddress((void**)&v,   g_v);
    cudaGetSymbolAddress((void**)&ctx, g_ctx);

    dim3 gg(1024 / 128, MROWS / 128);   // (8, 32)
    gemm_tc<<<gg, 256>>>(x, wq, bq, q);
    gemm_tc<<<gg, 256>>>(x, wk, bk, k);
    gemm_tc<<<gg, 256>>>(x, wv, bv, v);

    dim3 ga(Ss / 64, Bb * NHh);         // (32, 32)
    attn_kernel<<<ga, 256>>>();

    gemm_tc<<<gg, 256>>>(ctx, wo, bo, out);
}

// round 6
// speedup vs baseline: 5.5521x; 5.5521x over previous
#include <cuda_runtime.h>
#include <cstdint>
#include <math.h>

#define Bb 2
#define Ss 2048
#define Hh 1024
#define NHh 16
#define Dd 64
#define MROWS (Bb * Ss)   // 4096

typedef unsigned long long ull;

// Scratch (no cudaMalloc allowed): Q, K, V, ctx each [4096, 1024] fp32 = 16 MiB
__device__ float g_q[MROWS * Hh];
__device__ float g_k[MROWS * Hh];
__device__ float g_v[MROWS * Hh];
__device__ float g_ctx[MROWS * Hh];

// ===========================================================================
// f32x2 packed-math helpers (sm_100-family PTX, no 'a' feature needed)
// ===========================================================================
__device__ __forceinline__ ull pk2(float x, float y) {
    ull r;
    asm("mov.b64 %0, {%1, %2};" : "=l"(r) : "f"(x), "f"(y));
    return r;
}
__device__ __forceinline__ void upk2(ull v, float& x, float& y) {
    asm("mov.b64 {%0, %1}, %2;" : "=f"(x), "=f"(y) : "l"(v));
}
__device__ __forceinline__ ull ffma2(ull a, ull b, ull c) {
    ull d;
    asm("fma.rn.f32x2 %0, %1, %2, %3;" : "=l"(d) : "l"(a), "l"(b), "l"(c));
    return d;
}
__device__ __forceinline__ ull fmul2(ull a, ull b) {
    ull d;
    asm("mul.rn.f32x2 %0, %1, %2;" : "=l"(d) : "l"(a), "l"(b));
    return d;
}

// ===========================================================================
// GEMM (NT) with FFMA2: C[m][n] = sum_k A[m][k]*W[n][k] + bias[n]
// M=4096, N=1024, K=1024. Block 128x128, K-tile 16, 256 thr, 8x8/thread.
// Thread n-cols: {2*tx + 32*j + {0,1}}, j=0..3 -> conflict-free LDS64 pairs.
// ===========================================================================
__global__ void __launch_bounds__(256) gemm_f2(
    const float* __restrict__ A, const float* __restrict__ B,
    const float* __restrict__ bias, float* __restrict__ C)
{
    const int K = 1024, N = 1024;
    __shared__ float As[16][132];
    __shared__ float Bs[16][132];

    const int tid = threadIdx.x;
    const int tx = tid % 16;          // n direction
    const int ty = tid / 16;          // m direction
    const int m0 = blockIdx.y * 128;
    const int n0 = blockIdx.x * 128;

    const int lr = tid / 4;           // 0..63
    const int lc = (tid % 4) * 4;     // 0,4,8,12

    ull acc2[8][4];
#pragma unroll
    for (int i = 0; i < 8; i++)
#pragma unroll
        for (int j = 0; j < 4; j++) acc2[i][j] = 0ULL;

    for (int k0 = 0; k0 < K; k0 += 16) {
#pragma unroll
        for (int h = 0; h < 2; h++) {
            int r = lr + h * 64;
            float4 a = *(const float4*)&A[(size_t)(m0 + r) * K + k0 + lc];
            As[lc + 0][r] = a.x; As[lc + 1][r] = a.y;
            As[lc + 2][r] = a.z; As[lc + 3][r] = a.w;
            float4 b = *(const float4*)&B[(size_t)(n0 + r) * K + k0 + lc];
            Bs[lc + 0][r] = b.x; Bs[lc + 1][r] = b.y;
            Bs[lc + 2][r] = b.z; Bs[lc + 3][r] = b.w;
        }
        __syncthreads();

#pragma unroll
        for (int kk = 0; kk < 16; kk++) {
            float4 a0 = *(const float4*)&As[kk][ty * 8];
            float4 a1 = *(const float4*)&As[kk][ty * 8 + 4];
            ull ra2[8];
            ra2[0] = pk2(a0.x, a0.x); ra2[1] = pk2(a0.y, a0.y);
            ra2[2] = pk2(a0.z, a0.z); ra2[3] = pk2(a0.w, a0.w);
            ra2[4] = pk2(a1.x, a1.x); ra2[5] = pk2(a1.y, a1.y);
            ra2[6] = pk2(a1.z, a1.z); ra2[7] = pk2(a1.w, a1.w);
            ull rb2[4];
#pragma unroll
            for (int j = 0; j < 4; j++)
                rb2[j] = *(const ull*)&Bs[kk][2 * tx + 32 * j];
#pragma unroll
            for (int i = 0; i < 8; i++)
#pragma unroll
                for (int j = 0; j < 4; j++)
                    acc2[i][j] = ffma2(ra2[i], rb2[j], acc2[i][j]);
        }
        __syncthreads();
    }

#pragma unroll
    for (int i = 0; i < 8; i++) {
        int row = m0 + ty * 8 + i;
#pragma unroll
        for (int j = 0; j < 4; j++) {
            int col = n0 + 2 * tx + 32 * j;
            float2 bb = *(const float2*)&bias[col];
            float x, y;
            upk2(acc2[i][j], x, y);
            float2 c;
            c.x = x + bb.x;
            c.y = y + bb.y;
            *(float2*)&C[(size_t)row * N + col] = c;
        }
    }
}

// ===========================================================================
// Flash attention, register-blocked + FFMA2.
// Br=64, Bc=64, D=64, 128 threads. tm=tid/8 (16 row-groups), tn=tid%8.
// Thread rows: {tm + 16*i}, i=0..3.
// QK cols: {tn + 8*c}, c=0..7.   PV d-cols: pairs {2*tn + 16*c, +1}, c=0..3.
// Q/K in d-pair-interleaved smem (ull [32][65]); V row-major [64][68];
// P [64][72]. All inner-loop LDS are bank-conflict-free by construction.
// ===========================================================================
#define QKR 65
#define VR  68
#define PR  72
#define OFF_QP 0
#define OFF_KP (OFF_QP + 32 * QKR * 8)         // 16640
#define OFF_V  (OFF_KP + 32 * QKR * 8)         // 33280
#define OFF_P  (OFF_V + 64 * VR * 4)           // 50688
#define SMEM_ATTN (OFF_P + 64 * PR * 4)        // 69120

__global__ void __launch_bounds__(128) attn_f2()
{
    extern __shared__ char smem_raw[];
    ull*   sQp = (ull*)(smem_raw + OFF_QP);    // [dp*QKR + row]
    ull*   sKp = (ull*)(smem_raw + OFF_KP);    // [dp*QKR + col]
    float* sV  = (float*)(smem_raw + OFF_V);   // [k*VR + d]
    float* sP  = (float*)(smem_raw + OFF_P);   // [row*PR + col]

    const int bh = blockIdx.y;           // 0..31
    const int b  = bh / NHh;
    const int h  = bh % NHh;
    const int q0 = blockIdx.x * 64;

    const int tid = threadIdx.x;
    const int tm  = tid >> 3;            // 0..15
    const int tn  = tid & 7;             // 0..7

    const float* Qb = g_q + (size_t)(b * Ss) * Hh + h * Dd;
    const float* Kb = g_k + (size_t)(b * Ss) * Hh + h * Dd;
    const float* Vb = g_v + (size_t)(b * Ss) * Hh + h * Dd;

    // Load Q tile into d-pair layout: 64 rows x 16 float4
    for (int idx = tid; idx < 64 * 16; idx += 128) {
        int r = idx >> 4, f4 = idx & 15;
        float4 v = *(const float4*)&Qb[(size_t)(q0 + r) * Hh + f4 * 4];
        sQp[(2 * f4 + 0) * QKR + r] = *(ull*)&v.x;
        sQp[(2 * f4 + 1) * QKR + r] = *(ull*)&v.z;
    }

    float m[4], l[4];
    ull o2[4][4];
#pragma unroll
    for (int i = 0; i < 4; i++) {
        m[i] = -1e30f; l[i] = 0.f;
#pragma unroll
        for (int c = 0; c < 4; c++) o2[i][c] = 0ULL;
    }

    for (int kt = 0; kt < Ss; kt += 64) {
        __syncthreads();   // prev PV done reading sKp/sV/sP; Q visible (1st iter)
        for (int idx = tid; idx < 64 * 16; idx += 128) {
            int r = idx >> 4, f4 = idx & 15;
            float4 kv = *(const float4*)&Kb[(size_t)(kt + r) * Hh + f4 * 4];
            sKp[(2 * f4 + 0) * QKR + r] = *(ull*)&kv.x;
            sKp[(2 * f4 + 1) * QKR + r] = *(ull*)&kv.z;
            float4 vv = *(const float4*)&Vb[(size_t)(kt + r) * Hh + f4 * 4];
            *(float4*)&sV[r * VR + f4 * 4] = vv;
        }
        __syncthreads();

        // ---- S = Q K^T  (4 rows x 8 cols per thread, f32x2 over d) ----
        ull s2[4][8];
#pragma unroll
        for (int i = 0; i < 4; i++)
#pragma unroll
            for (int c = 0; c < 8; c++) s2[i][c] = 0ULL;

        for (int dp = 0; dp < 32; dp++) {
            ull q2[4], k2[8];
#pragma unroll
            for (int i = 0; i < 4; i++)
                q2[i] = sQp[dp * QKR + tm + 16 * i];
#pragma unroll
            for (int c = 0; c < 8; c++)
                k2[c] = sKp[dp * QKR + tn + 8 * c];
#pragma unroll
            for (int i = 0; i < 4; i++)
#pragma unroll
                for (int c = 0; c < 8; c++)
                    s2[i][c] = ffma2(q2[i], k2[c], s2[i][c]);
        }

        // ---- online softmax (per row; reduce across the 8 tn lanes) ----
#pragma unroll
        for (int i = 0; i < 4; i++) {
            float s[8];
            float mrow = -1e30f;
#pragma unroll
            for (int c = 0; c < 8; c++) {
                float lo, hi;
                upk2(s2[i][c], lo, hi);
                s[c] = (lo + hi) * 0.125f;     // 1/sqrt(64)
                mrow = fmaxf(mrow, s[c]);
            }
            mrow = fmaxf(mrow, __shfl_xor_sync(0xffffffffu, mrow, 1));
            mrow = fmaxf(mrow, __shfl_xor_sync(0xffffffffu, mrow, 2));
            mrow = fmaxf(mrow, __shfl_xor_sync(0xffffffffu, mrow, 4));

            float mnew  = fmaxf(m[i], mrow);
            float alpha = __expf(m[i] - mnew);
            float lsum = 0.f;
            int rowbase = (tm + 16 * i) * PR;
#pragma unroll
            for (int c = 0; c < 8; c++) {
                float p = __expf(s[c] - mnew);
                lsum += p;
                sP[rowbase + tn + 8 * c] = p;
            }
            lsum += __shfl_xor_sync(0xffffffffu, lsum, 1);
            lsum += __shfl_xor_sync(0xffffffffu, lsum, 2);
            lsum += __shfl_xor_sync(0xffffffffu, lsum, 4);
            l[i] = l[i] * alpha + lsum;
            m[i] = mnew;
            ull a2 = pk2(alpha, alpha);
#pragma unroll
            for (int c = 0; c < 4; c++) o2[i][c] = fmul2(o2[i][c], a2);
        }
        __syncthreads();   // sP fully written

        // ---- O += P V  (4 rows x 4 d-pairs per thread) ----
        for (int k = 0; k < 64; k++) {
            ull v2[4];
#pragma unroll
            for (int c = 0; c < 4; c++)
                v2[c] = *(const ull*)&sV[k * VR + 2 * tn + 16 * c];
#pragma unroll
            for (int i = 0; i < 4; i++) {
                float p = sP[(tm + 16 * i) * PR + k];
                ull p2 = pk2(p, p);
#pragma unroll
                for (int c = 0; c < 4; c++)
                    o2[i][c] = ffma2(p2, v2[c], o2[i][c]);
            }
        }
    }

    // Epilogue: normalize and write to concat layout [B*S, H]
#pragma unroll
    for (int i = 0; i < 4; i++) {
        const float inv = 1.f / l[i];
        const int row = q0 + tm + 16 * i;
        float* op = g_ctx + (size_t)(b * Ss + row) * Hh + h * Dd;
#pragma unroll
        for (int c = 0; c < 4; c++) {
            float x, y;
            upk2(o2[i][c], x, y);
            float2 w;
            w.x = x * inv; w.y = y * inv;
            *(float2*)&op[2 * tn + 16 * c] = w;
        }
    }
}

// ---------------------------------------------------------------------------
extern "C" void kernel_launch(void* const* d_in, const int* in_sizes, int n_in,
                              void* d_out, int out_size)
{
    const float* x  = (const float*)d_in[0];
    const float* wq = (const float*)d_in[1];
    const float* bq = (const float*)d_in[2];
    const float* wk = (const float*)d_in[3];
    const float* bk = (const float*)d_in[4];
    const float* wv = (const float*)d_in[5];
    const float* bv = (const float*)d_in[6];
    const float* wo = (const float*)d_in[7];
    const float* bo = (const float*)d_in[8];
    float* out = (float*)d_out;

    float *q, *k, *v, *ctx;
    cudaGetSymbolAddress((void**)&q,   g_q);
    cudaGetSymbolAddress((void**)&k,   g_k);
    cudaGetSymbolAddress((void**)&v,   g_v);
    cudaGetSymbolAddress((void**)&ctx, g_ctx);

    cudaFuncSetAttribute(attn_f2, cudaFuncAttributeMaxDynamicSharedMemorySize,
                         SMEM_ATTN);

    dim3 gg(1024 / 128, MROWS / 128);   // (8, 32)
    gemm_f2<<<gg, 256>>>(x, wq, bq, q);
    gemm_f2<<<gg, 256>>>(x, wk, bk, k);
    gemm_f2<<<gg, 256>>>(x, wv, bv, v);

    dim3 ga(Ss / 64, Bb * NHh);         // (32, 32)
    attn_f2<<<ga, 128, SMEM_ATTN>>>();

    gemm_f2<<<gg, 256>>>(ctx, wo, bo, out);
}

// round 8
// speedup vs baseline: 6.1379x; 1.1055x over previous
#include <cuda_runtime.h>
#include <cstdint>
#include <math.h>

#define Bb 2
#define Ss 2048
#define Hh 1024
#define NHh 16
#define Dd 64
#define MROWS (Bb * Ss)   // 4096

typedef unsigned long long ull;

// Scratch (no cudaMalloc allowed): Q, K, V, ctx each [4096, 1024] fp32 = 16 MiB
__device__ float g_q[MROWS * Hh];
__device__ float g_k[MROWS * Hh];
__device__ float g_v[MROWS * Hh];
__device__ float g_ctx[MROWS * Hh];

// ===========================================================================
// f32x2 packed-math helpers
// ===========================================================================
__device__ __forceinline__ ull pk2(float x, float y) {
    ull r;
    asm("mov.b64 %0, {%1, %2};" : "=l"(r) : "f"(x), "f"(y));
    return r;
}
__device__ __forceinline__ void upk2(ull v, float& x, float& y) {
    asm("mov.b64 {%0, %1}, %2;" : "=f"(x), "=f"(y) : "l"(v));
}
__device__ __forceinline__ ull ffma2(ull a, ull b, ull c) {
    ull d;
    asm("fma.rn.f32x2 %0, %1, %2, %3;" : "=l"(d) : "l"(a), "l"(b), "l"(c));
    return d;
}
__device__ __forceinline__ ull fmul2(ull a, ull b) {
    ull d;
    asm("mul.rn.f32x2 %0, %1, %2;" : "=l"(d) : "l"(a), "l"(b));
    return d;
}

// ===========================================================================
// GEMM core (NT, FFMA2, double-buffered): C[m][n] = sum_k A[m][k]W[n][k]+bias
// M=4096, N=1024, K=1024. Block 128x128, K-tile 16, 256 thr, 8x8/thread.
// ===========================================================================
__device__ __forceinline__ void gemm_core(
    const float* __restrict__ A, const float* __restrict__ W,
    const float* __restrict__ bias, float* __restrict__ C,
    float (*As)[16][132], float (*Bs)[16][132])
{
    const int K = 1024, N = 1024;
    const int tid = threadIdx.x;
    const int tx = tid % 16;          // n direction
    const int ty = tid / 16;          // m direction
    const int m0 = blockIdx.y * 128;
    const int n0 = blockIdx.x * 128;
    const int lr = tid / 4;           // 0..63
    const int lc = (tid % 4) * 4;     // 0,4,8,12

    ull acc2[8][4];
#pragma unroll
    for (int i = 0; i < 8; i++)
#pragma unroll
        for (int j = 0; j < 4; j++) acc2[i][j] = 0ULL;

    const float* Arow0 = A + (size_t)(m0 + lr) * K + lc;
    const float* Arow1 = A + (size_t)(m0 + lr + 64) * K + lc;
    const float* Brow0 = W + (size_t)(n0 + lr) * K + lc;
    const float* Brow1 = W + (size_t)(n0 + lr + 64) * K + lc;

    // prefetch + store tile 0
    {
        float4 a0 = *(const float4*)Arow0;
        float4 a1 = *(const float4*)Arow1;
        float4 b0 = *(const float4*)Brow0;
        float4 b1 = *(const float4*)Brow1;
        As[0][lc + 0][lr] = a0.x; As[0][lc + 1][lr] = a0.y;
        As[0][lc + 2][lr] = a0.z; As[0][lc + 3][lr] = a0.w;
        As[0][lc + 0][lr + 64] = a1.x; As[0][lc + 1][lr + 64] = a1.y;
        As[0][lc + 2][lr + 64] = a1.z; As[0][lc + 3][lr + 64] = a1.w;
        Bs[0][lc + 0][lr] = b0.x; Bs[0][lc + 1][lr] = b0.y;
        Bs[0][lc + 2][lr] = b0.z; Bs[0][lc + 3][lr] = b0.w;
        Bs[0][lc + 0][lr + 64] = b1.x; Bs[0][lc + 1][lr + 64] = b1.y;
        Bs[0][lc + 2][lr + 64] = b1.z; Bs[0][lc + 3][lr + 64] = b1.w;
    }
    __syncthreads();

    for (int t = 0; t < 64; t++) {
        const int cur = t & 1;
        float4 na0, na1, nb0, nb1;
        if (t < 63) {
            int k1 = (t + 1) * 16;
            na0 = *(const float4*)&Arow0[k1];
            na1 = *(const float4*)&Arow1[k1];
            nb0 = *(const float4*)&Brow0[k1];
            nb1 = *(const float4*)&Brow1[k1];
        }

#pragma unroll
        for (int kk = 0; kk < 16; kk++) {
            float4 a0 = *(const float4*)&As[cur][kk][ty * 8];
            float4 a1 = *(const float4*)&As[cur][kk][ty * 8 + 4];
            ull ra2[8];
            ra2[0] = pk2(a0.x, a0.x); ra2[1] = pk2(a0.y, a0.y);
            ra2[2] = pk2(a0.z, a0.z); ra2[3] = pk2(a0.w, a0.w);
            ra2[4] = pk2(a1.x, a1.x); ra2[5] = pk2(a1.y, a1.y);
            ra2[6] = pk2(a1.z, a1.z); ra2[7] = pk2(a1.w, a1.w);
            ull rb2[4];
#pragma unroll
            for (int j = 0; j < 4; j++)
                rb2[j] = *(const ull*)&Bs[cur][kk][2 * tx + 32 * j];
#pragma unroll
            for (int i = 0; i < 8; i++)
#pragma unroll
                for (int j = 0; j < 4; j++)
                    acc2[i][j] = ffma2(ra2[i], rb2[j], acc2[i][j]);
        }

        if (t < 63) {
            const int nb = cur ^ 1;
            As[nb][lc + 0][lr] = na0.x; As[nb][lc + 1][lr] = na0.y;
            As[nb][lc + 2][lr] = na0.z; As[nb][lc + 3][lr] = na0.w;
            As[nb][lc + 0][lr + 64] = na1.x; As[nb][lc + 1][lr + 64] = na1.y;
            As[nb][lc + 2][lr + 64] = na1.z; As[nb][lc + 3][lr + 64] = na1.w;
            Bs[nb][lc + 0][lr] = nb0.x; Bs[nb][lc + 1][lr] = nb0.y;
            Bs[nb][lc + 2][lr] = nb0.z; Bs[nb][lc + 3][lr] = nb0.w;
            Bs[nb][lc + 0][lr + 64] = nb1.x; Bs[nb][lc + 1][lr + 64] = nb1.y;
            Bs[nb][lc + 2][lr + 64] = nb1.z; Bs[nb][lc + 3][lr + 64] = nb1.w;
            __syncthreads();
        }
    }

#pragma unroll
    for (int i = 0; i < 8; i++) {
        int row = m0 + ty * 8 + i;
#pragma unroll
        for (int j = 0; j < 4; j++) {
            int col = n0 + 2 * tx + 32 * j;
            float2 bb = *(const float2*)&bias[col];
            float x, y;
            upk2(acc2[i][j], x, y);
            float2 c;
            c.x = x + bb.x;
            c.y = y + bb.y;
            *(float2*)&C[(size_t)row * N + col] = c;
        }
    }
}

// Fused QKV projection: grid.z selects {Q,K,V}
__global__ void __launch_bounds__(256) qkv_f2(
    const float* __restrict__ x,
    const float* __restrict__ wq, const float* __restrict__ bq,
    const float* __restrict__ wk, const float* __restrict__ bk,
    const float* __restrict__ wv, const float* __restrict__ bv)
{
    __shared__ float As[2][16][132];
    __shared__ float Bs[2][16][132];
    const float* W; const float* bias; float* C;
    if (blockIdx.z == 0)      { W = wq; bias = bq; C = g_q; }
    else if (blockIdx.z == 1) { W = wk; bias = bk; C = g_k; }
    else                      { W = wv; bias = bv; C = g_v; }
    gemm_core(x, W, bias, C, As, Bs);
}

__global__ void __launch_bounds__(256) oproj_f2(
    const float* __restrict__ wo, const float* __restrict__ bo,
    float* __restrict__ out)
{
    __shared__ float As[2][16][132];
    __shared__ float Bs[2][16][132];
    gemm_core(g_ctx, wo, bo, out, As, Bs);
}

// ===========================================================================
// Flash attention: Br=128, Bc=64, D=64, 256 threads, 2 CTAs/SM.
// tm=tid/8 (0..31), tn=tid%8. QK rows {tm+32i}, cols {tn+8c}.
// PV d-pairs {2tn+16c,+1}. All hot LDS are <=8-distinct-address broadcasts.
// VR=68 (mult of 4) keeps the float4 V stores 16B-aligned (VR=66 crashed R7).
// ===========================================================================
#define QPR 129
#define KPR 65
#define VR  68
#define PR  72
#define OFF_QP 0
#define OFF_KP (32 * QPR * 8)                  // 33024
#define OFF_V  (OFF_KP + 32 * KPR * 8)         // 49664
#define OFF_P  (OFF_V + 64 * VR * 4)           // 67072
#define SMEM_ATTN (OFF_P + 128 * PR * 4)       // 103936

__global__ void __launch_bounds__(256, 2) attn_f2()
{
    extern __shared__ char smem_raw[];
    ull*   sQp = (ull*)(smem_raw + OFF_QP);    // [dp*QPR + row], dp=0..31
    ull*   sKp = (ull*)(smem_raw + OFF_KP);    // [dp*KPR + col]
    float* sV  = (float*)(smem_raw + OFF_V);   // [k*VR + d]
    float* sP  = (float*)(smem_raw + OFF_P);   // [row*PR + col]

    const int bh = blockIdx.y;           // 0..31
    const int b  = bh / NHh;
    const int h  = bh % NHh;
    const int q0 = blockIdx.x * 128;

    const int tid = threadIdx.x;
    const int tm  = tid >> 3;            // 0..31
    const int tn  = tid & 7;             // 0..7

    const float* Qb = g_q + (size_t)(b * Ss) * Hh + h * Dd;
    const float* Kb = g_k + (size_t)(b * Ss) * Hh + h * Dd;
    const float* Vb = g_v + (size_t)(b * Ss) * Hh + h * Dd;

    // Load Q tile (128 rows x 64 d) into d-pair layout
    for (int idx = tid; idx < 128 * 16; idx += 256) {
        int r = idx >> 4, f4 = idx & 15;
        float4 v = *(const float4*)&Qb[(size_t)(q0 + r) * Hh + f4 * 4];
        sQp[(2 * f4 + 0) * QPR + r] = *(ull*)&v.x;
        sQp[(2 * f4 + 1) * QPR + r] = *(ull*)&v.z;
    }

    float m[4], l[4];
    ull o2[4][4];
#pragma unroll
    for (int i = 0; i < 4; i++) {
        m[i] = -1e30f; l[i] = 0.f;
#pragma unroll
        for (int c = 0; c < 4; c++) o2[i][c] = 0ULL;
    }

    for (int kt = 0; kt < Ss; kt += 64) {
        __syncthreads();   // prev PV done with sKp/sV/sP; Q stores visible
        for (int idx = tid; idx < 64 * 16; idx += 256) {
            int r = idx >> 4, f4 = idx & 15;
            float4 kv = *(const float4*)&Kb[(size_t)(kt + r) * Hh + f4 * 4];
            sKp[(2 * f4 + 0) * KPR + r] = *(ull*)&kv.x;
            sKp[(2 * f4 + 1) * KPR + r] = *(ull*)&kv.z;
            float4 vv = *(const float4*)&Vb[(size_t)(kt + r) * Hh + f4 * 4];
            *(float4*)&sV[r * VR + f4 * 4] = vv;
        }
        __syncthreads();

        // ---- S = Q K^T  (4 rows x 8 cols per thread) ----
        ull s2[4][8];
#pragma unroll
        for (int i = 0; i < 4; i++)
#pragma unroll
            for (int c = 0; c < 8; c++) s2[i][c] = 0ULL;

#pragma unroll 4
        for (int dp = 0; dp < 32; dp++) {
            ull q2[4], k2[8];
#pragma unroll
            for (int i = 0; i < 4; i++)
                q2[i] = sQp[dp * QPR + tm + 32 * i];
#pragma unroll
            for (int c = 0; c < 8; c++)
                k2[c] = sKp[dp * KPR + tn + 8 * c];
#pragma unroll
            for (int i = 0; i < 4; i++)
#pragma unroll
                for (int c = 0; c < 8; c++)
                    s2[i][c] = ffma2(q2[i], k2[c], s2[i][c]);
        }

        // ---- online softmax (per row; reduce across 8 tn lanes) ----
#pragma unroll
        for (int i = 0; i < 4; i++) {
            float s[8];
            float mrow = -1e30f;
#pragma unroll
            for (int c = 0; c < 8; c++) {
                float lo, hi;
                upk2(s2[i][c], lo, hi);
                s[c] = (lo + hi) * 0.125f;     // 1/sqrt(64)
                mrow = fmaxf(mrow, s[c]);
            }
            mrow = fmaxf(mrow, __shfl_xor_sync(0xffffffffu, mrow, 1));
            mrow = fmaxf(mrow, __shfl_xor_sync(0xffffffffu, mrow, 2));
            mrow = fmaxf(mrow, __shfl_xor_sync(0xffffffffu, mrow, 4));

            float mnew  = fmaxf(m[i], mrow);
            float alpha = __expf(m[i] - mnew);
            float lsum = 0.f;
            int rowbase = (tm + 32 * i) * PR;
#pragma unroll
            for (int c = 0; c < 8; c++) {
                float p = __expf(s[c] - mnew);
                lsum += p;
                sP[rowbase + tn + 8 * c] = p;
            }
            lsum += __shfl_xor_sync(0xffffffffu, lsum, 1);
            lsum += __shfl_xor_sync(0xffffffffu, lsum, 2);
            lsum += __shfl_xor_sync(0xffffffffu, lsum, 4);
            l[i] = l[i] * alpha + lsum;
            m[i] = mnew;
            ull a2 = pk2(alpha, alpha);
#pragma unroll
            for (int c = 0; c < 4; c++) o2[i][c] = fmul2(o2[i][c], a2);
        }
        __syncthreads();   // sP fully written

        // ---- O += P V  (4 rows x 4 d-pairs per thread) ----
#pragma unroll 4
        for (int k = 0; k < 64; k++) {
            ull v2[4];
#pragma unroll
            for (int c = 0; c < 4; c++)
                v2[c] = *(const ull*)&sV[k * VR + 2 * tn + 16 * c];
#pragma unroll
            for (int i = 0; i < 4; i++) {
                float p = sP[(tm + 32 * i) * PR + k];
                ull p2 = pk2(p, p);
#pragma unroll
                for (int c = 0; c < 4; c++)
                    o2[i][c] = ffma2(p2, v2[c], o2[i][c]);
            }
        }
    }

    // Epilogue: normalize and write to concat layout [B*S, H]
#pragma unroll
    for (int i = 0; i < 4; i++) {
        const float inv = 1.f / l[i];
        const int row = q0 + tm + 32 * i;
        float* op = g_ctx + (size_t)(b * Ss + row) * Hh + h * Dd;
#pragma unroll
        for (int c = 0; c < 4; c++) {
            float x, y;
            upk2(o2[i][c], x, y);
            float2 w;
            w.x = x * inv; w.y = y * inv;
            *(float2*)&op[2 * tn + 16 * c] = w;
        }
    }
}

// ---------------------------------------------------------------------------
extern "C" void kernel_launch(void* const* d_in, const int* in_sizes, int n_in,
                              void* d_out, int out_size)
{
    const float* x  = (const float*)d_in[0];
    const float* wq = (const float*)d_in[1];
    const float* bq = (const float*)d_in[2];
    const float* wk = (const float*)d_in[3];
    const float* bk = (const float*)d_in[4];
    const float* wv = (const float*)d_in[5];
    const float* bv = (const float*)d_in[6];
    const float* wo = (const float*)d_in[7];
    const float* bo = (const float*)d_in[8];
    float* out = (float*)d_out;

    cudaFuncSetAttribute(attn_f2, cudaFuncAttributeMaxDynamicSharedMemorySize,
                         SMEM_ATTN);

    dim3 gq(1024 / 128, MROWS / 128, 3);   // (8, 32, 3)
    qkv_f2<<<gq, 256>>>(x, wq, bq, wk, bk, wv, bv);

    dim3 ga(Ss / 128, Bb * NHh);           // (16, 32)
    attn_f2<<<ga, 256, SMEM_ATTN>>>();

    dim3 gg(1024 / 128, MROWS / 128);      // (8, 32)
    oproj_f2<<<gg, 256>>>(wo, bo, out);
}